// round 10
// baseline (speedup 1.0000x reference)
#include <cuda_runtime.h>
#include <math.h>

// Problem constants
#define B_   64
#define S_   4096
#define ENC_ 512
#define DEC_ 512

#define NCHUNK 8                  // CTAs (e-tiles / S-chunks) per batch
#define CHUNK  (S_ / NCHUNK)      // 512 rows per chunk
#define NCTOT  (B_ * NCHUNK)      // 512 total CTAs

// ---- scratch (no allocations allowed; __device__ globals) ----
__device__ float g_sub[B_ * ENC_];          // dec @ W^T            (128 KB)
__device__ float g_logits[B_ * S_];         // raw attention logits (1 MB)
__device__ float g_pm[NCTOT];               // per-chunk running max
__device__ float g_pl[NCTOT];               // per-chunk running denom
__device__ float g_pacc[NCTOT * ENC_];      // per-chunk weighted-sum vec (1 MB)
__device__ unsigned g_cnt[B_];              // chunks-done tickets   (self-resetting)
__device__ unsigned g_subcnt[B_];           // sub-tiles-done tickets (self-resetting)

// ============================================================
// Single fused kernel. grid = (NCHUNK, B_) = (8, 64), block = 256.
// Phase A: CTA (c,b) computes sub[b, c*64 .. c*64+63]  (R2 sub tile)
// Spin:    wait until all 8 tiles of batch b are published (L2 atomics)
// Phase B: untouched R7/R2 streaming loop + online softmax
// Phase C: fused finalize via last-CTA-done; last CTA resets counters
// Progress-safety: deps are intra-batch only; resident CTAs of earlier
// batches always complete, freeing SMs for any waiting CTAs.
// ============================================================
__global__ __launch_bounds__(256) void attn_fused(const float* __restrict__ dec,
                                                  const float* __restrict__ W,
                                                  const float* __restrict__ enc,
                                                  float* __restrict__ out) {
    const int c    = blockIdx.x;          // e-tile / chunk index
    const int b    = blockIdx.y;
    const int tid  = threadIdx.x;
    const int w    = tid >> 5;
    const int lane = tid & 31;

    __shared__ float subsm[ENC_];
    __shared__ float accsm[8][ENC_];      // 16 KB
    __shared__ float msm[8], lsm[8];
    __shared__ bool  is_last;

    // ---------- Phase A: compute this CTA's 64-wide sub tile ----------
    for (int i = tid; i < DEC_; i += 256) subsm[i] = dec[b * DEC_ + i];
    __syncthreads();

    {
        const float4* d4 = (const float4*)subsm;
        float4 dv[4];
#pragma unroll
        for (int j = 0; j < 4; j++) dv[j] = d4[lane + 32 * j];

        const int e0 = c * 64 + w * 8;    // warp handles e0 .. e0+7
#pragma unroll
        for (int i = 0; i < 8; i++) {
            const int e = e0 + i;
            const float4* Wr = (const float4*)(W + (size_t)e * DEC_);
            float s = 0.f;
#pragma unroll
            for (int j = 0; j < 4; j++) {
                float4 wv = Wr[lane + 32 * j];
                s += wv.x * dv[j].x + wv.y * dv[j].y + wv.z * dv[j].z + wv.w * dv[j].w;
            }
#pragma unroll
            for (int o = 16; o > 0; o >>= 1) s += __shfl_xor_sync(0xffffffffu, s, o);
            if (lane == 0) g_sub[b * ENC_ + e] = s;
        }
    }

    // publish tile, then wait for the other 7 tiles of batch b
    __threadfence();
    __syncthreads();
    if (tid == 0) {
        atomicAdd(&g_subcnt[b], 1u);
        while (atomicAdd(&g_subcnt[b], 0u) < (unsigned)NCHUNK) __nanosleep(32);
    }
    __syncthreads();

    // reload full sub[b] through L2 (bypass possibly-stale L1)
    __syncthreads();
    for (int i = tid; i < ENC_; i += 256) subsm[i] = __ldcg(&g_sub[b * ENC_ + i]);
    __syncthreads();

    // ---------- Phase B: streaming pass (exact R2/R7 loop) ----------
    float4 subr[4];
    const float4* sub4 = (const float4*)subsm;
#pragma unroll
    for (int j = 0; j < 4; j++) subr[j] = sub4[lane + 32 * j];

    float m = -1e30f;
    float l = 0.f;
    float4 acc[4];
#pragma unroll
    for (int j = 0; j < 4; j++) acc[j] = make_float4(0.f, 0.f, 0.f, 0.f);

    const int s0 = c * CHUNK;
    const float* encb = enc + (size_t)b * S_ * ENC_;

    for (int r = w; r < CHUNK; r += 8) {
        const int s = s0 + r;
        const float4* er = (const float4*)(encb + (size_t)s * ENC_);

        float4 ev[4];
#pragma unroll
        for (int j = 0; j < 4; j++) ev[j] = __ldcs(&er[lane + 32 * j]);  // streaming

        float dot = 0.f;
#pragma unroll
        for (int j = 0; j < 4; j++) {
            dot += ev[j].x * subr[j].x + ev[j].y * subr[j].y +
                   ev[j].z * subr[j].z + ev[j].w * subr[j].w;
        }
#pragma unroll
        for (int o = 16; o > 0; o >>= 1) dot += __shfl_xor_sync(0xffffffffu, dot, o);

        if (lane == 0) g_logits[b * S_ + s] = dot;

        const float mn    = fmaxf(m, dot);
        const float scale = __expf(m - mn);
        const float p     = __expf(dot - mn);
        l = l * scale + p;
#pragma unroll
        for (int j = 0; j < 4; j++) {
            acc[j].x = acc[j].x * scale + p * ev[j].x;
            acc[j].y = acc[j].y * scale + p * ev[j].y;
            acc[j].z = acc[j].z * scale + p * ev[j].z;
            acc[j].w = acc[j].w * scale + p * ev[j].w;
        }
        m = mn;
    }

    // spill warp state to smem
    float4* arow = (float4*)accsm[w];
#pragma unroll
    for (int j = 0; j < 4; j++) arow[lane + 32 * j] = acc[j];
    if (lane == 0) { msm[w] = m; lsm[w] = l; }
    __syncthreads();

    // block merge
    float M = -1e30f;
#pragma unroll
    for (int ww = 0; ww < 8; ww++) M = fmaxf(M, msm[ww]);
    float L = 0.f;
    float wts[8];
#pragma unroll
    for (int ww = 0; ww < 8; ww++) {
        wts[ww] = __expf(msm[ww] - M);
        L += lsm[ww] * wts[ww];
    }

    const int cid = b * NCHUNK + c;
    if (tid == 0) { g_pm[cid] = M; g_pl[cid] = L; }

    for (int e = tid; e < ENC_; e += 256) {
        float a = 0.f;
#pragma unroll
        for (int ww = 0; ww < 8; ww++) a += accsm[ww][e] * wts[ww];
        g_pacc[(size_t)cid * ENC_ + e] = a;
    }

    // ---------- Phase C: last-CTA-done finalize ----------
    __threadfence();
    __syncthreads();
    if (tid == 0) {
        unsigned r = atomicAdd(&g_cnt[b], 1u);
        is_last = (r == NCHUNK - 1);
    }
    __syncthreads();
    if (!is_last) return;

    __threadfence();
    float Mg = -1e30f;
#pragma unroll
    for (int cc = 0; cc < NCHUNK; cc++) Mg = fmaxf(Mg, __ldcg(&g_pm[b * NCHUNK + cc]));
    float Lg = 0.f;
    float wg[NCHUNK];
#pragma unroll
    for (int cc = 0; cc < NCHUNK; cc++) {
        wg[cc] = __expf(__ldcg(&g_pm[b * NCHUNK + cc]) - Mg);
        Lg += __ldcg(&g_pl[b * NCHUNK + cc]) * wg[cc];
    }
    const float invL = 1.f / Lg;

    const float* lg = g_logits + b * S_;
    float* attn_out = out + (size_t)b * S_;
    for (int s = tid; s < S_; s += 256)
        attn_out[s] = __expf(__ldcg(&lg[s]) - Mg) * invL;

    float* sum_out = out + (size_t)B_ * S_ + (size_t)b * ENC_;
    for (int e = tid; e < ENC_; e += 256) {
        float a = 0.f;
#pragma unroll
        for (int cc = 0; cc < NCHUNK; cc++)
            a += __ldcg(&g_pacc[(size_t)(b * NCHUNK + cc) * ENC_ + e]) * wg[cc];
        sum_out[e] = a * invL;
    }

    // reset counters for next graph replay (safe: all batch-b CTAs are past
    // both the spin and the ticket; nobody touches these again this launch)
    __syncthreads();
    if (tid == 0) { g_cnt[b] = 0; g_subcnt[b] = 0; }
}

// ============================================================
extern "C" void kernel_launch(void* const* d_in, const int* in_sizes, int n_in,
                              void* d_out, int out_size) {
    const float* dec = (const float*)d_in[0];  // [64,1,512]
    const float* enc = (const float*)d_in[1];  // [64,4096,512]
    const float* W   = (const float*)d_in[2];  // [512,512]
    float* out = (float*)d_out;

    attn_fused<<<dim3(NCHUNK, B_), 256>>>(dec, W, enc, out);
}

// round 11
// speedup vs baseline: 1.1054x; 1.1054x over previous
#include <cuda_runtime.h>
#include <cuda_pipeline.h>
#include <math.h>

// Problem constants
#define B_   64
#define S_   4096
#define ENC_ 512
#define DEC_ 512

#define NCHUNK 8                  // S chunks per batch
#define CHUNK  (S_ / NCHUNK)      // 512 rows per chunk
#define NCTOT  (B_ * NCHUNK)      // 512 total chunks

// ---- scratch (no allocations allowed; __device__ globals) ----
__device__ float g_sub[B_ * ENC_];          // dec @ W^T            (128 KB)
__device__ float g_logits[B_ * S_];         // raw attention logits (1 MB)
__device__ float g_pm[NCTOT];               // per-chunk running max
__device__ float g_pl[NCTOT];               // per-chunk running denom
__device__ float g_pacc[NCTOT * ENC_];      // per-chunk weighted-sum vec (1 MB)
__device__ unsigned g_cnt[B_];              // last-CTA-done tickets (reset by sub_kernel)

// ============================================================
// Kernel 1: sub[b,e] = sum_d dec[b,d] * W[e,d]   (R2 version, best measured)
// grid = (8, 64), block = 256. Also resets g_cnt (runs before pass1).
// ============================================================
__global__ __launch_bounds__(256) void sub_kernel(const float* __restrict__ dec,
                                                  const float* __restrict__ W) {
    const int et   = blockIdx.x;
    const int b    = blockIdx.y;
    const int tid  = threadIdx.x;
    const int w    = tid >> 5;
    const int lane = tid & 31;

    if (et == 0 && tid == 0) g_cnt[b] = 0;

    __shared__ float dsm[DEC_];
    for (int i = tid; i < DEC_; i += 256) dsm[i] = dec[b * DEC_ + i];
    __syncthreads();

    const float4* d4 = (const float4*)dsm;
    float4 dv[4];
#pragma unroll
    for (int j = 0; j < 4; j++) dv[j] = d4[lane + 32 * j];

    const int e0 = et * 64 + w * 8;
#pragma unroll
    for (int i = 0; i < 8; i++) {
        const int e = e0 + i;
        const float4* Wr = (const float4*)(W + (size_t)e * DEC_);
        float s = 0.f;
#pragma unroll
        for (int j = 0; j < 4; j++) {
            float4 wv = Wr[lane + 32 * j];
            s += wv.x * dv[j].x + wv.y * dv[j].y + wv.z * dv[j].z + wv.w * dv[j].w;
        }
#pragma unroll
        for (int o = 16; o > 0; o >>= 1) s += __shfl_xor_sync(0xffffffffu, s, o);
        if (lane == 0) g_sub[b * ENC_ + e] = s;
    }
}

// ============================================================
// Kernel 2: streaming pass with cp.async double-buffering + fused finalize.
// grid = (NCHUNK, B_) = (8, 64), block = 256 (8 warps, warp-per-row).
// Each warp owns a 2x2KB smem ring; row k+8 streams in via LDGSTS while
// row k is computed from smem. All smem addresses are thread-local
// (lane reads exactly what it wrote) -> only __syncwarp needed.
// ============================================================
__global__ __launch_bounds__(256) void attn_pass1(const float* __restrict__ enc,
                                                  float* __restrict__ out) {
    const int c    = blockIdx.x;          // chunk index within batch
    const int b    = blockIdx.y;
    const int tid  = threadIdx.x;
    const int w    = tid >> 5;
    const int lane = tid & 31;

    __shared__ float  subsm[ENC_];
    __shared__ float  accsm[8][ENC_];     // 16 KB
    __shared__ float4 kbuf[8][2][128];    // 8 warps x 2 bufs x 2KB = 32 KB
    __shared__ float  msm[8], lsm[8];
    __shared__ bool   is_last;

    for (int i = tid; i < ENC_; i += 256) subsm[i] = g_sub[b * ENC_ + i];
    __syncthreads();

    float4 subr[4];
    const float4* sub4 = (const float4*)subsm;
#pragma unroll
    for (int j = 0; j < 4; j++) subr[j] = sub4[lane + 32 * j];

    float m = -1e30f;
    float l = 0.f;
    float4 acc[4];
#pragma unroll
    for (int j = 0; j < 4; j++) acc[j] = make_float4(0.f, 0.f, 0.f, 0.f);

    const int s0 = c * CHUNK;
    const float* encb = enc + (size_t)b * S_ * ENC_;

    // prologue: prefetch first row into buf 0
    {
        const float4* er = (const float4*)(encb + (size_t)(s0 + w) * ENC_);
#pragma unroll
        for (int j = 0; j < 4; j++)
            __pipeline_memcpy_async(&kbuf[w][0][lane + 32 * j], &er[lane + 32 * j], 16);
        __pipeline_commit();
    }

    int cur = 0;
    for (int r = w; r < CHUNK; r += 8) {
        const int s = s0 + r;

        // prefetch next row (clamped; tail prefetch is a cheap redundant read)
        const int snx = (r + 8 < CHUNK) ? (s + 8) : (s0 + w);
        {
            const float4* er = (const float4*)(encb + (size_t)snx * ENC_);
#pragma unroll
            for (int j = 0; j < 4; j++)
                __pipeline_memcpy_async(&kbuf[w][cur ^ 1][lane + 32 * j], &er[lane + 32 * j], 16);
            __pipeline_commit();
        }

        // wait for current buffer (newest group may stay in flight)
        __pipeline_wait_prior(1);
        __syncwarp();

        float4 ev[4];
#pragma unroll
        for (int j = 0; j < 4; j++) ev[j] = kbuf[w][cur][lane + 32 * j];

        float dot = 0.f;
#pragma unroll
        for (int j = 0; j < 4; j++) {
            dot += ev[j].x * subr[j].x + ev[j].y * subr[j].y +
                   ev[j].z * subr[j].z + ev[j].w * subr[j].w;
        }
#pragma unroll
        for (int o = 16; o > 0; o >>= 1) dot += __shfl_xor_sync(0xffffffffu, dot, o);

        if (lane == 0) g_logits[b * S_ + s] = dot;

        const float mn    = fmaxf(m, dot);
        const float scale = __expf(m - mn);
        const float p     = __expf(dot - mn);
        l = l * scale + p;
#pragma unroll
        for (int j = 0; j < 4; j++) {
            acc[j].x = acc[j].x * scale + p * ev[j].x;
            acc[j].y = acc[j].y * scale + p * ev[j].y;
            acc[j].z = acc[j].z * scale + p * ev[j].z;
            acc[j].w = acc[j].w * scale + p * ev[j].w;
        }
        m = mn;
        cur ^= 1;
    }
    __pipeline_wait_prior(0);             // drain tail prefetch

    // spill warp state to smem
    float4* arow = (float4*)accsm[w];
#pragma unroll
    for (int j = 0; j < 4; j++) arow[lane + 32 * j] = acc[j];
    if (lane == 0) { msm[w] = m; lsm[w] = l; }
    __syncthreads();

    // block merge
    float M = -1e30f;
#pragma unroll
    for (int ww = 0; ww < 8; ww++) M = fmaxf(M, msm[ww]);
    float L = 0.f;
    float wts[8];
#pragma unroll
    for (int ww = 0; ww < 8; ww++) {
        wts[ww] = __expf(msm[ww] - M);
        L += lsm[ww] * wts[ww];
    }

    const int cid = b * NCHUNK + c;
    if (tid == 0) { g_pm[cid] = M; g_pl[cid] = L; }

    for (int e = tid; e < ENC_; e += 256) {
        float a = 0.f;
#pragma unroll
        for (int ww = 0; ww < 8; ww++) a += accsm[ww][e] * wts[ww];
        g_pacc[(size_t)cid * ENC_ + e] = a;
    }

    // ---- last-CTA-done finalize (proven R7 pattern) ----
    __threadfence();
    __syncthreads();
    if (tid == 0) {
        unsigned r = atomicAdd(&g_cnt[b], 1u);
        is_last = (r == NCHUNK - 1);
    }
    __syncthreads();
    if (!is_last) return;

    __threadfence();
    float Mg = -1e30f;
#pragma unroll
    for (int cc = 0; cc < NCHUNK; cc++) Mg = fmaxf(Mg, g_pm[b * NCHUNK + cc]);
    float Lg = 0.f;
    float wg[NCHUNK];
#pragma unroll
    for (int cc = 0; cc < NCHUNK; cc++) {
        wg[cc] = __expf(g_pm[b * NCHUNK + cc] - Mg);
        Lg += g_pl[b * NCHUNK + cc] * wg[cc];
    }
    const float invL = 1.f / Lg;

    const float* lg = g_logits + b * S_;
    float* attn_out = out + (size_t)b * S_;
    for (int s = tid; s < S_; s += 256)
        attn_out[s] = __expf(lg[s] - Mg) * invL;

    float* sum_out = out + (size_t)B_ * S_ + (size_t)b * ENC_;
    for (int e = tid; e < ENC_; e += 256) {
        float a = 0.f;
#pragma unroll
        for (int cc = 0; cc < NCHUNK; cc++)
            a += g_pacc[(size_t)(b * NCHUNK + cc) * ENC_ + e] * wg[cc];
        sum_out[e] = a * invL;
    }
}

// ============================================================
extern "C" void kernel_launch(void* const* d_in, const int* in_sizes, int n_in,
                              void* d_out, int out_size) {
    const float* dec = (const float*)d_in[0];  // [64,1,512]
    const float* enc = (const float*)d_in[1];  // [64,4096,512]
    const float* W   = (const float*)d_in[2];  // [512,512]
    float* out = (float*)d_out;

    sub_kernel<<<dim3(ENC_ / 64, B_), 256>>>(dec, W);
    attn_pass1<<<dim3(NCHUNK, B_), 256>>>(enc, out);
}

// round 12
// speedup vs baseline: 1.2652x; 1.1446x over previous
#include <cuda_runtime.h>
#include <math.h>

// Problem constants
#define B_   64
#define S_   4096
#define ENC_ 512
#define DEC_ 512

#define NCHUNK 8                  // S chunks per batch
#define CHUNK  (S_ / NCHUNK)      // 512 rows per chunk
#define NCTOT  (B_ * NCHUNK)      // 512 total chunks

// ---- scratch (no allocations allowed; __device__ globals) ----
__device__ float g_sub[B_ * ENC_];          // dec @ W^T            (128 KB)
__device__ float g_logits[B_ * S_];         // raw attention logits (1 MB)
__device__ float g_pm[NCTOT];               // per-chunk running max
__device__ float g_pl[NCTOT];               // per-chunk running denom
__device__ float g_pacc[NCTOT * ENC_];      // per-chunk weighted-sum vec (1 MB)
__device__ unsigned g_cnt[B_];              // last-CTA-done tickets (reset by sub_kernel)

// ============================================================
// Kernel 1: sub[b,e] = sum_d dec[b,d] * W[e,d]   (R2 version, best measured)
// grid = (8, 64), block = 256. Also resets g_cnt (runs before pass1).
// ============================================================
__global__ __launch_bounds__(256) void sub_kernel(const float* __restrict__ dec,
                                                  const float* __restrict__ W) {
    const int et   = blockIdx.x;
    const int b    = blockIdx.y;
    const int tid  = threadIdx.x;
    const int w    = tid >> 5;
    const int lane = tid & 31;

    if (et == 0 && tid == 0) g_cnt[b] = 0;

    __shared__ float dsm[DEC_];
    for (int i = tid; i < DEC_; i += 256) dsm[i] = dec[b * DEC_ + i];
    __syncthreads();

    const float4* d4 = (const float4*)dsm;
    float4 dv[4];
#pragma unroll
    for (int j = 0; j < 4; j++) dv[j] = d4[lane + 32 * j];

    const int e0 = et * 64 + w * 8;
#pragma unroll
    for (int i = 0; i < 8; i++) {
        const int e = e0 + i;
        const float4* Wr = (const float4*)(W + (size_t)e * DEC_);
        float s = 0.f;
#pragma unroll
        for (int j = 0; j < 4; j++) {
            float4 wv = Wr[lane + 32 * j];
            s += wv.x * dv[j].x + wv.y * dv[j].y + wv.z * dv[j].z + wv.w * dv[j].w;
        }
#pragma unroll
        for (int o = 16; o > 0; o >>= 1) s += __shfl_xor_sync(0xffffffffu, s, o);
        if (lane == 0) g_sub[b * ENC_ + e] = s;
    }
}

// ============================================================
// Kernel 2: streaming pass (EXACT R7 loop) + L2 prefetch 2 rows ahead.
// grid = (NCHUNK, B_) = (8, 64), block = 256 (8 warps, warp-per-row).
// prefetch.global.L2 costs no registers / no scoreboard: the later LDG
// hits L2 (~250cyc) instead of DRAM (~600+), shrinking exposed latency.
// ============================================================
__global__ __launch_bounds__(256) void attn_pass1(const float* __restrict__ enc,
                                                  float* __restrict__ out) {
    const int c    = blockIdx.x;          // chunk index within batch
    const int b    = blockIdx.y;
    const int tid  = threadIdx.x;
    const int w    = tid >> 5;
    const int lane = tid & 31;

    __shared__ float subsm[ENC_];
    __shared__ float accsm[8][ENC_];      // 16 KB
    __shared__ float msm[8], lsm[8];
    __shared__ bool  is_last;

    for (int i = tid; i < ENC_; i += 256) subsm[i] = g_sub[b * ENC_ + i];
    __syncthreads();

    float4 subr[4];
    const float4* sub4 = (const float4*)subsm;
#pragma unroll
    for (int j = 0; j < 4; j++) subr[j] = sub4[lane + 32 * j];

    float m = -1e30f;
    float l = 0.f;
    float4 acc[4];
#pragma unroll
    for (int j = 0; j < 4; j++) acc[j] = make_float4(0.f, 0.f, 0.f, 0.f);

    const int s0 = c * CHUNK;
    const float* encb = enc + (size_t)b * S_ * ENC_;
    const bool pf_lane = ((lane & 7) == 0);   // lanes 0,8,16,24: 1 prefetch per 128B line

    // prime the prefetch pipeline: rows r=w and r=w+8 for this warp
    if (pf_lane) {
        const float4* p0 = (const float4*)(encb + (size_t)(s0 + w) * ENC_);
        const float4* p1 = (const float4*)(encb + (size_t)(s0 + w + 8) * ENC_);
#pragma unroll
        for (int j = 0; j < 4; j++) {
            asm volatile("prefetch.global.L2 [%0];" :: "l"(&p0[lane + 32 * j]));
            asm volatile("prefetch.global.L2 [%0];" :: "l"(&p1[lane + 32 * j]));
        }
    }

    for (int r = w; r < CHUNK; r += 8) {
        const int s = s0 + r;
        const float4* er = (const float4*)(encb + (size_t)s * ENC_);

        // prefetch row r+16 (2 iterations ahead) into L2 — no reg cost
        if (pf_lane && r + 16 < CHUNK) {
            const float4* pf = (const float4*)(encb + (size_t)(s + 16) * ENC_);
#pragma unroll
            for (int j = 0; j < 4; j++)
                asm volatile("prefetch.global.L2 [%0];" :: "l"(&pf[lane + 32 * j]));
        }

        float4 ev[4];
#pragma unroll
        for (int j = 0; j < 4; j++) ev[j] = __ldcs(&er[lane + 32 * j]);  // streaming

        float dot = 0.f;
#pragma unroll
        for (int j = 0; j < 4; j++) {
            dot += ev[j].x * subr[j].x + ev[j].y * subr[j].y +
                   ev[j].z * subr[j].z + ev[j].w * subr[j].w;
        }
#pragma unroll
        for (int o = 16; o > 0; o >>= 1) dot += __shfl_xor_sync(0xffffffffu, dot, o);

        if (lane == 0) g_logits[b * S_ + s] = dot;

        const float mn    = fmaxf(m, dot);
        const float scale = __expf(m - mn);
        const float p     = __expf(dot - mn);
        l = l * scale + p;
#pragma unroll
        for (int j = 0; j < 4; j++) {
            acc[j].x = acc[j].x * scale + p * ev[j].x;
            acc[j].y = acc[j].y * scale + p * ev[j].y;
            acc[j].z = acc[j].z * scale + p * ev[j].z;
            acc[j].w = acc[j].w * scale + p * ev[j].w;
        }
        m = mn;
    }

    // spill warp state to smem
    float4* arow = (float4*)accsm[w];
#pragma unroll
    for (int j = 0; j < 4; j++) arow[lane + 32 * j] = acc[j];
    if (lane == 0) { msm[w] = m; lsm[w] = l; }
    __syncthreads();

    // block merge
    float M = -1e30f;
#pragma unroll
    for (int ww = 0; ww < 8; ww++) M = fmaxf(M, msm[ww]);
    float L = 0.f;
    float wts[8];
#pragma unroll
    for (int ww = 0; ww < 8; ww++) {
        wts[ww] = __expf(msm[ww] - M);
        L += lsm[ww] * wts[ww];
    }

    const int cid = b * NCHUNK + c;
    if (tid == 0) { g_pm[cid] = M; g_pl[cid] = L; }

    for (int e = tid; e < ENC_; e += 256) {
        float a = 0.f;
#pragma unroll
        for (int ww = 0; ww < 8; ww++) a += accsm[ww][e] * wts[ww];
        g_pacc[(size_t)cid * ENC_ + e] = a;
    }

    // ---- last-CTA-done finalize (proven R7 pattern) ----
    __threadfence();
    __syncthreads();
    if (tid == 0) {
        unsigned r = atomicAdd(&g_cnt[b], 1u);
        is_last = (r == NCHUNK - 1);
    }
    __syncthreads();
    if (!is_last) return;

    __threadfence();
    float Mg = -1e30f;
#pragma unroll
    for (int cc = 0; cc < NCHUNK; cc++) Mg = fmaxf(Mg, g_pm[b * NCHUNK + cc]);
    float Lg = 0.f;
    float wg[NCHUNK];
#pragma unroll
    for (int cc = 0; cc < NCHUNK; cc++) {
        wg[cc] = __expf(g_pm[b * NCHUNK + cc] - Mg);
        Lg += g_pl[b * NCHUNK + cc] * wg[cc];
    }
    const float invL = 1.f / Lg;

    const float* lg = g_logits + b * S_;
    float* attn_out = out + (size_t)b * S_;
    for (int s = tid; s < S_; s += 256)
        attn_out[s] = __expf(lg[s] - Mg) * invL;

    float* sum_out = out + (size_t)B_ * S_ + (size_t)b * ENC_;
    for (int e = tid; e < ENC_; e += 256) {
        float a = 0.f;
#pragma unroll
        for (int cc = 0; cc < NCHUNK; cc++)
            a += g_pacc[(size_t)(b * NCHUNK + cc) * ENC_ + e] * wg[cc];
        sum_out[e] = a * invL;
    }
}

// ============================================================
extern "C" void kernel_launch(void* const* d_in, const int* in_sizes, int n_in,
                              void* d_out, int out_size) {
    const float* dec = (const float*)d_in[0];  // [64,1,512]
    const float* enc = (const float*)d_in[1];  // [64,4096,512]
    const float* W   = (const float*)d_in[2];  // [512,512]
    float* out = (float*)d_out;

    sub_kernel<<<dim3(ENC_ / 64, B_), 256>>>(dec, W);
    attn_pass1<<<dim3(NCHUNK, B_), 256>>>(enc, out);
}